// round 5
// baseline (speedup 1.0000x reference)
#include <cuda_runtime.h>
#include <cstdint>

// ---------------------------------------------------------------------------
// LeWinAttention round 5 (= round 4 resubmit after infra failure):
// pipelined tf32 mma.sync GEMMs. CTA tile 128x128, BK=32, 2-stage smem
// double buffer, XOR-swizzled smem. tcgen05 unavailable (target sm_103, no 'a').
// ---------------------------------------------------------------------------

__device__ float g_qkv[402653184];   // 8192*64*768  (1.5 GB)
__device__ float g_aout[134217728];  // 8192*64*256  (512 MB)

__device__ __forceinline__ unsigned f2tf32(float f) {
    unsigned u; asm("cvt.rna.tf32.f32 %0, %1;" : "=r"(u) : "f"(f)); return u;
}
__device__ __forceinline__ void mma_tf32(float* d, const unsigned* a, const unsigned* b) {
    asm volatile(
        "mma.sync.aligned.m16n8k8.row.col.f32.tf32.tf32.f32 "
        "{%0,%1,%2,%3}, {%4,%5,%6,%7}, {%8,%9}, {%0,%1,%2,%3};"
        : "+f"(d[0]), "+f"(d[1]), "+f"(d[2]), "+f"(d[3])
        : "r"(a[0]), "r"(a[1]), "r"(a[2]), "r"(a[3]), "r"(b[0]), "r"(b[1]));
}

// smem stage: A[128][32] + B[128][32] tf32 words, XOR swizzle on 16B chunks.
#define STAGE_F 8192      // floats per stage (A 4096 + B 4096)

__global__ void __launch_bounds__(256, 1)
gemm_tc2_kernel(const float* __restrict__ A, const float* __restrict__ W,
                const float* __restrict__ bias, float* __restrict__ C, int Nc)
{
    extern __shared__ float sm[];

    const int t    = threadIdx.x;
    const int lane = t & 31;
    const int gid  = lane >> 2;
    const int tig  = lane & 3;
    const int w    = t >> 5;
    const int wm   = w & 3;       // 4 warps in m
    const int wn   = w >> 2;      // 2 warps in n
    const size_t mBase = (size_t)blockIdx.y * 128;
    const int    nBase = blockIdx.x * 128;

    const int lrow = t >> 3;          // 0..31 (+32*i)
    const int lchk = t & 7;           // 16B chunk index 0..7

    const float* Ap = A + (mBase + lrow) * 256 + (lchk << 2);
    const float* Wp = W + ((size_t)nBase + lrow) * 256 + (lchk << 2);

    float acc[2][8][4];
#pragma unroll
    for (int mt = 0; mt < 2; mt++)
#pragma unroll
        for (int nt = 0; nt < 8; nt++)
#pragma unroll
            for (int i = 0; i < 4; i++) acc[mt][nt][i] = 0.f;

    float4 ar[4], br[4];
#pragma unroll
    for (int i = 0; i < 4; i++) ar[i] = *(const float4*)(Ap + i * 8192);
#pragma unroll
    for (int i = 0; i < 4; i++) br[i] = *(const float4*)(Wp + i * 8192);

    // ---- store one stage (cvt fp32->tf32, XOR-swizzled chunks)
    auto stage_store = [&](int s, const float4* a4, const float4* b4) {
        float* base = sm + s * STAGE_F;
#pragma unroll
        for (int i = 0; i < 4; i++) {
            int row = lrow + (i << 5);
            int chk = lchk ^ (row & 7);
            uint4 u = make_uint4(f2tf32(a4[i].x), f2tf32(a4[i].y),
                                 f2tf32(a4[i].z), f2tf32(a4[i].w));
            *(uint4*)(base + row * 32 + (chk << 2)) = u;
        }
        float* bb = base + 4096;
#pragma unroll
        for (int i = 0; i < 4; i++) {
            int row = lrow + (i << 5);
            int chk = lchk ^ (row & 7);
            uint4 u = make_uint4(f2tf32(b4[i].x), f2tf32(b4[i].y),
                                 f2tf32(b4[i].z), f2tf32(b4[i].w));
            *(uint4*)(bb + row * 32 + (chk << 2)) = u;
        }
    };

    stage_store(0, ar, br);

    const int r0a = wm * 32 + gid;          // + mt*16 (+8)
    const int n0a = wn * 64 + gid;          // + nt*8

#pragma unroll 2
    for (int it = 0; it < 8; it++) {
        __syncthreads();  // stage (it&1) visible to all; prev compute done

        if (it + 1 < 8) {
            const int k0 = (it + 1) << 5;
#pragma unroll
            for (int i = 0; i < 4; i++) ar[i] = *(const float4*)(Ap + k0 + i * 8192);
#pragma unroll
            for (int i = 0; i < 4; i++) br[i] = *(const float4*)(Wp + k0 + i * 8192);
        }

        const float* as = sm + (it & 1) * STAGE_F;
        const float* bs = as + 4096;

#pragma unroll
        for (int kk = 0; kk < 4; kk++) {
            const int c0 = ((kk << 1) ^ gid) << 2;        // even chunk (k8..k8+3)
            const int c1 = (((kk << 1) | 1) ^ gid) << 2;  // odd chunk  (k8+4..k8+7)
            unsigned af[2][4], bf[8][2];
#pragma unroll
            for (int mt = 0; mt < 2; mt++) {
                const float* r = as + (r0a + (mt << 4)) * 32;
                af[mt][0] = __float_as_uint(r[c0 + tig]);
                af[mt][1] = __float_as_uint(r[256 + c0 + tig]);   // +8 rows
                af[mt][2] = __float_as_uint(r[c1 + tig]);
                af[mt][3] = __float_as_uint(r[256 + c1 + tig]);
            }
#pragma unroll
            for (int nt = 0; nt < 8; nt++) {
                const float* r = bs + (n0a + (nt << 3)) * 32;
                bf[nt][0] = __float_as_uint(r[c0 + tig]);
                bf[nt][1] = __float_as_uint(r[c1 + tig]);
            }
#pragma unroll
            for (int mt = 0; mt < 2; mt++)
#pragma unroll
                for (int nt = 0; nt < 8; nt++)
                    mma_tf32(acc[mt][nt], af[mt], bf[nt]);
        }

        if (it + 1 < 8)
            stage_store((it + 1) & 1, ar, br);  // opposite buffer; safe post-sync
    }

    // ---- epilogue: + bias, float2 stores
#pragma unroll
    for (int mt = 0; mt < 2; mt++) {
#pragma unroll
        for (int nt = 0; nt < 8; nt++) {
            int col = nBase + wn * 64 + nt * 8 + (tig << 1);
            float b0 = bias[col], b1 = bias[col + 1];
            size_t r0 = mBase + wm * 32 + mt * 16 + gid;
            *(float2*)(C + r0 * Nc + col) =
                make_float2(acc[mt][nt][0] + b0, acc[mt][nt][1] + b1);
            *(float2*)(C + (r0 + 8) * Nc + col) =
                make_float2(acc[mt][nt][2] + b0, acc[mt][nt][3] + b1);
        }
    }
}

// ---------------------------------------------------------------------------
// Attention: one CTA per (head, window). fp32 path (unchanged).
// ---------------------------------------------------------------------------
__global__ void __launch_bounds__(128)
attn_kernel(const float* __restrict__ qkv, const float* __restrict__ table,
            const int* __restrict__ rpi, float* __restrict__ aout)
{
    __shared__ float sq[64][36];
    __shared__ float sk[64][36];
    __shared__ float sv[64][36];
    __shared__ float sp[64][65];

    const int h = blockIdx.x;
    const int b = blockIdx.y;
    const int t = threadIdx.x;

    const float* base = qkv + (size_t)b * 64 * 768 + h * 32;
    for (int idx = t; idx < 64 * 8; idx += 128) {
        int n  = idx >> 3;
        int c4 = (idx & 7) << 2;
        const float* rp = base + n * 768 + c4;
        float4 q4 = *(const float4*)(rp);
        float4 k4 = *(const float4*)(rp + 256);
        float4 v4 = *(const float4*)(rp + 512);
        *(float4*)&sq[n][c4] = q4;
        *(float4*)&sk[n][c4] = k4;
        *(float4*)&sv[n][c4] = v4;
    }
    __syncthreads();

    const int n    = t & 63;
    const int half = t >> 6;

    float qreg[32];
#pragma unroll
    for (int d4 = 0; d4 < 8; d4++) {
        float4 q4 = *(const float4*)&sq[n][d4 << 2];
        qreg[d4 * 4 + 0] = q4.x; qreg[d4 * 4 + 1] = q4.y;
        qreg[d4 * 4 + 2] = q4.z; qreg[d4 * 4 + 3] = q4.w;
    }

    const float scale = 0.17677669529663687f;
#pragma unroll 4
    for (int mm = 0; mm < 32; mm++) {
        int m = (half << 5) + mm;
        float s = 0.f;
#pragma unroll
        for (int d4 = 0; d4 < 8; d4++) {
            float4 k4 = *(const float4*)&sk[m][d4 << 2];
            s += qreg[d4 * 4 + 0] * k4.x + qreg[d4 * 4 + 1] * k4.y
               + qreg[d4 * 4 + 2] * k4.z + qreg[d4 * 4 + 3] * k4.w;
        }
        int idx = rpi[n * 64 + m];
        sp[n][m] = s * scale + table[idx * 8 + h];
    }
    __syncthreads();

    if (t < 64) {
        float mx = -1e30f;
#pragma unroll
        for (int m = 0; m < 64; m++) mx = fmaxf(mx, sp[t][m]);
        float sum = 0.f;
#pragma unroll
        for (int m = 0; m < 64; m++) {
            float e = __expf(sp[t][m] - mx);
            sp[t][m] = e;
            sum += e;
        }
        float inv = 1.f / sum;
#pragma unroll
        for (int m = 0; m < 64; m++) sp[t][m] *= inv;
    }
    __syncthreads();

    float o[16];
#pragma unroll
    for (int i = 0; i < 16; i++) o[i] = 0.f;
    const int dBase = half << 4;
    for (int m = 0; m < 64; m++) {
        float p = sp[n][m];
#pragma unroll
        for (int d4 = 0; d4 < 4; d4++) {
            float4 v4 = *(const float4*)&sv[m][dBase + (d4 << 2)];
            o[d4 * 4 + 0] += p * v4.x; o[d4 * 4 + 1] += p * v4.y;
            o[d4 * 4 + 2] += p * v4.z; o[d4 * 4 + 3] += p * v4.w;
        }
    }
    float* op = aout + ((size_t)b * 64 + n) * 256 + h * 32 + dBase;
#pragma unroll
    for (int d4 = 0; d4 < 4; d4++)
        *(float4*)(op + (d4 << 2)) =
            make_float4(o[d4 * 4 + 0], o[d4 * 4 + 1], o[d4 * 4 + 2], o[d4 * 4 + 3]);
}

// ---------------------------------------------------------------------------
extern "C" void kernel_launch(void* const* d_in, const int* in_sizes, int n_in,
                              void* d_out, int out_size)
{
    const float* x   = (const float*)d_in[0];
    const float* qw  = (const float*)d_in[1];
    const float* qb  = (const float*)d_in[2];
    const float* pw  = (const float*)d_in[3];
    const float* pb  = (const float*)d_in[4];
    const float* tab = (const float*)d_in[5];
    const int*   rpi = (const int*)d_in[6];
    float* out = (float*)d_out;

    float* qkv  = nullptr;
    float* aout = nullptr;
    cudaGetSymbolAddress((void**)&qkv,  g_qkv);
    cudaGetSymbolAddress((void**)&aout, g_aout);

    const int smemBytes = 2 * STAGE_F * sizeof(float);  // 64 KB
    cudaFuncSetAttribute(gemm_tc2_kernel,
                         cudaFuncAttributeMaxDynamicSharedMemorySize, smemBytes);

    // QKV projection: [524288,256] @ [768,256]^T + b
    dim3 g1(768 / 128, (8192 * 64) / 128);   // (6, 4096)
    gemm_tc2_kernel<<<g1, 256, smemBytes>>>(x, qw, qb, qkv, 768);

    // Windowed attention
    dim3 g2(8, 8192);
    attn_kernel<<<g2, 128>>>(qkv, tab, rpi, aout);

    // Output projection: [524288,256] @ [256,256]^T + b
    dim3 g3(256 / 128, (8192 * 64) / 128);   // (2, 4096)
    gemm_tc2_kernel<<<g3, 256, smemBytes>>>(aout, pw, pb, out, 256);
}